// round 1
// baseline (speedup 1.0000x reference)
#include <cuda_runtime.h>

// Sinkhorn distance, N=M=4096, D=2, P=1, eps=0.1, 50 iterations.
// Single persistent kernel, software grid barrier, all math in a
// log2 domain pre-scaled by log2(e)/eps.

#define NN      4096
#define NCTA    128
#define NT      1024
#define NWARP   32
#define RPC     32          // rows (or cols) owned per CTA = NN / NCTA
#define CHUNK   128         // j-chunk per warp = NN / NWARP
#define ITERS   50

#define SCALEF      14.426950408889634f    // log2(e) / eps, eps = 0.1
#define INV_SCALEF  0.06931471805599453f   // eps * ln(2)  (C = C_tilde * this)
#define LMU2        (-11.9999409054f)      // log2(1/4096 + 1e-8)

__device__ float sk_g_u[NN];
__device__ float sk_g_v[NN];
__device__ float sk_g_cost[NCTA];
__device__ unsigned int sk_bar_count;
__device__ volatile unsigned int sk_bar_phase;

__device__ __forceinline__ float ex2f(float v) {
    float r; asm("ex2.approx.f32 %0, %1;" : "=f"(r) : "f"(v)); return r;
}
__device__ __forceinline__ float lg2f(float v) {
    float r; asm("lg2.approx.f32 %0, %1;" : "=f"(r) : "f"(v)); return r;
}

// Classic release/acquire software grid barrier. All threads call with the
// same monotonically increasing target. Requires all NCTA CTAs co-resident
// (128 CTAs <= 148 SMs, 1 CTA/SM at this smem/reg footprint).
__device__ __forceinline__ void grid_barrier(unsigned int target) {
    __threadfence();
    __syncthreads();
    if (threadIdx.x == 0) {
        unsigned int t = atomicAdd(&sk_bar_count, 1u);
        if (t == NCTA - 1) {
            sk_bar_count = 0;
            __threadfence();
            sk_bar_phase = target;
        } else {
            while (sk_bar_phase < target) { }
        }
    }
    __syncthreads();
}

__global__ void sk_init_kernel() {
    int t = blockIdx.x * blockDim.x + threadIdx.x;
    if (t == 0) { sk_bar_count = 0; sk_bar_phase = 0; }
    for (int i = t; i < NN; i += gridDim.x * blockDim.x) {
        sk_g_u[i] = 0.f;
        sk_g_v[i] = 0.f;
    }
}

__global__ void __launch_bounds__(NT, 1)
sk_persist_kernel(const float* __restrict__ x, const float* __restrict__ y,
                  float* __restrict__ out) {
    extern __shared__ float4 sp[];
    float4* sx = sp;        // {X0s, X1s, u_tilde, pad}
    float4* sy = sp + NN;   // {Y0s, Y1s, v_tilde, pad}
    __shared__ float part[NWARP][32];
    __shared__ float red[NWARP];

    const int tid  = threadIdx.x;
    const int lane = tid & 31;
    const int wid  = tid >> 5;
    const int cta  = blockIdx.x;
    const int rbase = cta * RPC;

    // Load + prescale all points into shared (immutable across iterations).
    for (int i = tid; i < NN; i += NT) {
        sx[i] = make_float4(x[2 * i] * SCALEF, x[2 * i + 1] * SCALEF, 0.f, 0.f);
        sy[i] = make_float4(y[2 * i] * SCALEF, y[2 * i + 1] * SCALEF, 0.f, 0.f);
    }
    __syncthreads();

    const float X0 = sx[rbase + lane].x;
    const float X1 = sx[rbase + lane].y;
    const float Y0 = sy[rbase + lane].x;
    const float Y1 = sy[rbase + lane].y;

    unsigned int phase = 0;

    for (int it = 0; it < ITERS; ++it) {
        // ---------- u pass: u_i = LMU2 - log2( sum_j 2^{v_j - C_ij} ) ----------
        for (int j = tid; j < NN; j += NT) sy[j].z = __ldcg(&sk_g_v[j]);
        __syncthreads();
        {
            const float4* p = sy + wid * CHUNK;
            float a0 = 0.f, a1 = 0.f, a2 = 0.f, a3 = 0.f;
            #pragma unroll 4
            for (int k = 0; k < CHUNK; k += 4) {
                float4 e0 = p[k + 0], e1 = p[k + 1], e2 = p[k + 2], e3 = p[k + 3];
                a0 += ex2f(e0.z - (fabsf(X0 - e0.x) + fabsf(X1 - e0.y)));
                a1 += ex2f(e1.z - (fabsf(X0 - e1.x) + fabsf(X1 - e1.y)));
                a2 += ex2f(e2.z - (fabsf(X0 - e2.x) + fabsf(X1 - e2.y)));
                a3 += ex2f(e3.z - (fabsf(X0 - e3.x) + fabsf(X1 - e3.y)));
            }
            part[wid][lane] = (a0 + a1) + (a2 + a3);
        }
        __syncthreads();
        if (wid == 0) {
            float s = 0.f;
            #pragma unroll
            for (int w = 0; w < NWARP; ++w) s += part[w][lane];
            __stcg(&sk_g_u[rbase + lane], LMU2 - lg2f(s));
        }
        grid_barrier(++phase);

        // ---------- v pass: v_j = LMU2 - log2( sum_i 2^{u_i - C_ij} ) ----------
        for (int i = tid; i < NN; i += NT) sx[i].z = __ldcg(&sk_g_u[i]);
        __syncthreads();
        {
            const float4* p = sx + wid * CHUNK;
            float a0 = 0.f, a1 = 0.f, a2 = 0.f, a3 = 0.f;
            #pragma unroll 4
            for (int k = 0; k < CHUNK; k += 4) {
                float4 e0 = p[k + 0], e1 = p[k + 1], e2 = p[k + 2], e3 = p[k + 3];
                a0 += ex2f(e0.z - (fabsf(Y0 - e0.x) + fabsf(Y1 - e0.y)));
                a1 += ex2f(e1.z - (fabsf(Y0 - e1.x) + fabsf(Y1 - e1.y)));
                a2 += ex2f(e2.z - (fabsf(Y0 - e2.x) + fabsf(Y1 - e2.y)));
                a3 += ex2f(e3.z - (fabsf(Y0 - e3.x) + fabsf(Y1 - e3.y)));
            }
            part[wid][lane] = (a0 + a1) + (a2 + a3);
        }
        __syncthreads();
        if (wid == 0) {
            float s = 0.f;
            #pragma unroll
            for (int w = 0; w < NWARP; ++w) s += part[w][lane];
            __stcg(&sk_g_v[rbase + lane], LMU2 - lg2f(s));
        }
        grid_barrier(++phase);
    }

    // ---------- final: pi = 2^{u_i + v_j - C_ij}, C, cost ----------
    for (int j = tid; j < NN; j += NT) sy[j].z = __ldcg(&sk_g_v[j]);
    for (int i = tid; i < NN; i += NT) sx[i].z = __ldcg(&sk_g_u[i]);
    __syncthreads();

    const size_t NM = (size_t)NN * NN;
    float* pi_out = out + 1;
    float* c_out  = out + 1 + NM;

    float cacc = 0.f;
    for (int r = 0; r < RPC; ++r) {
        const int i = rbase + r;
        const float4 X = sx[i];
        const size_t off = (size_t)i * NN;
        for (int j = tid; j < NN; j += NT) {
            float4 Yj = sy[j];
            float ct = fabsf(X.x - Yj.x) + fabsf(X.y - Yj.y);
            float pi = ex2f(X.z + Yj.z - ct);
            float c  = ct * INV_SCALEF;
            pi_out[off + j] = pi;
            c_out[off + j]  = c;
            cacc += pi * c;
        }
    }
    // Deterministic block reduction of cost partial.
    #pragma unroll
    for (int o = 16; o > 0; o >>= 1) cacc += __shfl_xor_sync(0xffffffffu, cacc, o);
    if (lane == 0) red[wid] = cacc;
    __syncthreads();
    if (wid == 0) {
        float s = red[lane];
        #pragma unroll
        for (int o = 16; o > 0; o >>= 1) s += __shfl_xor_sync(0xffffffffu, s, o);
        if (lane == 0) __stcg(&sk_g_cost[cta], s);
    }
    grid_barrier(++phase);

    if (cta == 0 && wid == 0) {
        float s = 0.f;
        #pragma unroll
        for (int b = lane; b < NCTA; b += 32) s += __ldcg(&sk_g_cost[b]);
        #pragma unroll
        for (int o = 16; o > 0; o >>= 1) s += __shfl_xor_sync(0xffffffffu, s, o);
        if (lane == 0) out[0] = s;   // cost ** (1/P) with P = 1
    }
}

extern "C" void kernel_launch(void* const* d_in, const int* in_sizes, int n_in,
                              void* d_out, int out_size) {
    (void)in_sizes; (void)n_in; (void)out_size;
    const float* x = (const float*)d_in[0];
    const float* y = (const float*)d_in[1];
    float* out = (float*)d_out;

    const size_t smem = 2 * (size_t)NN * sizeof(float4);   // 128 KB
    cudaFuncSetAttribute(sk_persist_kernel,
                         cudaFuncAttributeMaxDynamicSharedMemorySize, (int)smem);

    sk_init_kernel<<<8, 512>>>();
    sk_persist_kernel<<<NCTA, NT, smem>>>(x, y, out);
}

// round 2
// speedup vs baseline: 1.0840x; 1.0840x over previous
#include <cuda_runtime.h>

// Sinkhorn distance, N=M=4096, D=2, P=1, eps=0.1, 50 iterations.
// Persistent kernel, software grid barrier, log2 domain pre-scaled by log2(e)/eps.
// Inner loop uses packed f32x2 adds (2 elements/step); coords stored negated+scaled
// in shared so subtract folds into packed add.

#define NN      4096
#define NCTA    128
#define NT      1024
#define NWARP   32
#define RPC     32          // rows (or cols) owned per CTA
#define PPW     64          // float2-pairs per warp per pass = (NN/NWARP)/2
#define ITERS   50

#define SCALEF      14.426950408889634f    // log2(e)/eps
#define INV_SCALEF  0.06931471805599453f   // eps*ln(2)
#define LMU2        (-11.9999409054f)      // log2(1/4096 + 1e-8)

typedef unsigned long long ull;

__device__ float sk_g_u[NN];
__device__ float sk_g_v[NN];
__device__ float sk_g_cost[NCTA];
__device__ unsigned int sk_bar_count;
__device__ volatile unsigned int sk_bar_phase;

__device__ __forceinline__ float ex2f(float v) {
    float r; asm("ex2.approx.f32 %0, %1;" : "=f"(r) : "f"(v)); return r;
}
__device__ __forceinline__ float lg2f(float v) {
    float r; asm("lg2.approx.f32 %0, %1;" : "=f"(r) : "f"(v)); return r;
}
__device__ __forceinline__ ull fadd2(ull a, ull b) {
    ull r; asm("add.rn.f32x2 %0, %1, %2;" : "=l"(r) : "l"(a), "l"(b)); return r;
}
__device__ __forceinline__ ull pk(float lo, float hi) {
    ull r; asm("mov.b64 %0, {%1, %2};" : "=l"(r) : "f"(lo), "f"(hi)); return r;
}
__device__ __forceinline__ void upk(ull v, float& lo, float& hi) {
    asm("mov.b64 {%0, %1}, %2;" : "=f"(lo), "=f"(hi) : "l"(v));
}

__device__ __forceinline__ void grid_barrier(unsigned int target) {
    __threadfence();
    __syncthreads();
    if (threadIdx.x == 0) {
        unsigned int t = atomicAdd(&sk_bar_count, 1u);
        if (t == NCTA - 1) {
            sk_bar_count = 0;
            __threadfence();
            sk_bar_phase = target;
        } else {
            while (sk_bar_phase < target) { }
        }
    }
    __syncthreads();
}

__global__ void sk_init_kernel() {
    int t = blockIdx.x * blockDim.x + threadIdx.x;
    if (t == 0) { sk_bar_count = 0; sk_bar_phase = 0; }
    for (int i = t; i < NN; i += gridDim.x * blockDim.x) {
        sk_g_u[i] = 0.f;
        sk_g_v[i] = 0.f;
    }
}

// One 2-element inner step: acc += 2^{v - |X0-y0| - |X1-y1|} for a point pair.
// c = {-y0a, -y0b, -y1a, -y1b} (negated, pre-scaled), vp = {v_a, v_b}.
__device__ __forceinline__ void sk_step(ull& acc, float4 c, float2 vp, ull X0p, ull X1p) {
    ull d0 = fadd2(X0p, pk(c.x, c.y));
    ull d1 = fadd2(X1p, pk(c.z, c.w));
    float d0l, d0h, d1l, d1h;
    upk(d0, d0l, d0h);
    upk(d1, d1l, d1h);
    float sl = -fabsf(d0l) - fabsf(d1l);   // FADD with -|.| operand modifiers
    float sh = -fabsf(d0h) - fabsf(d1h);
    ull arg = fadd2(pk(vp.x, vp.y), pk(sl, sh));
    float al, ah;
    upk(arg, al, ah);
    acc = fadd2(acc, pk(ex2f(al), ex2f(ah)));
}

__global__ void __launch_bounds__(NT, 1)
sk_persist_kernel(const float* __restrict__ x, const float* __restrict__ y,
                  float* __restrict__ out) {
    extern __shared__ float4 smem_raw[];
    float4* sxc = smem_raw;                         // 2048 float4, 32KB: {-x0a,-x0b,-x1a,-x1b}
    float4* syc = smem_raw + NN / 2;                // 2048 float4, 32KB
    float*  su  = (float*)(smem_raw + NN);          // 4096 floats, 16KB
    float*  sv  = su + NN;                          // 4096 floats, 16KB
    __shared__ float part[NWARP * 33];
    __shared__ float red[NWARP];

    const int tid  = threadIdx.x;
    const int lane = tid & 31;
    const int wid  = tid >> 5;
    const int cta  = blockIdx.x;
    const int rbase = cta * RPC;

    // Prologue: negated, pre-scaled coords in pair-interleaved layout.
    for (int p = tid; p < NN / 2; p += NT) {
        float4 r = ((const float4*)x)[p];   // {x0_2p, x1_2p, x0_2p1, x1_2p1}
        sxc[p] = make_float4(-SCALEF * r.x, -SCALEF * r.z, -SCALEF * r.y, -SCALEF * r.w);
        float4 q = ((const float4*)y)[p];
        syc[p] = make_float4(-SCALEF * q.x, -SCALEF * q.z, -SCALEF * q.y, -SCALEF * q.w);
    }
    __syncthreads();

    // Row constants (positive, scaled) straight from global.
    const int myrow = rbase + lane;
    const float X0 = x[2 * myrow] * SCALEF;
    const float X1 = x[2 * myrow + 1] * SCALEF;
    const float Y0 = y[2 * myrow] * SCALEF;
    const float Y1 = y[2 * myrow + 1] * SCALEF;
    const ull X0p = pk(X0, X0), X1p = pk(X1, X1);
    const ull Y0p = pk(Y0, Y0), Y1p = pk(Y1, Y1);

    unsigned int phase = 0;

    for (int it = 0; it < ITERS; ++it) {
        // ===== u pass: u_i = LMU2 - log2( sum_j 2^{v_j - C_ij} ) =====
        ((float4*)sv)[tid] = __ldcg((const float4*)sk_g_v + tid);
        __syncthreads();
        {
            const float4* cb = syc + wid * PPW;
            const float2* vb = (const float2*)sv + wid * PPW;
            ull a0 = 0, a1 = 0, a2 = 0, a3 = 0;
            #pragma unroll 4
            for (int k = 0; k < PPW; k += 4) {
                sk_step(a0, cb[k + 0], vb[k + 0], X0p, X1p);
                sk_step(a1, cb[k + 1], vb[k + 1], X0p, X1p);
                sk_step(a2, cb[k + 2], vb[k + 2], X0p, X1p);
                sk_step(a3, cb[k + 3], vb[k + 3], X0p, X1p);
            }
            ull t = fadd2(fadd2(a0, a1), fadd2(a2, a3));
            float tl, th; upk(t, tl, th);
            part[wid * 33 + lane] = tl + th;
        }
        __syncthreads();
        {   // warp `wid` reduces row `wid` (transposed, stride-33 conflict-free)
            float pv = part[lane * 33 + wid];
            #pragma unroll
            for (int o = 16; o > 0; o >>= 1) pv += __shfl_xor_sync(0xffffffffu, pv, o);
            if (lane == 0) __stcg(&sk_g_u[rbase + wid], LMU2 - lg2f(pv));
        }
        grid_barrier(++phase);

        // ===== v pass: v_j = LMU2 - log2( sum_i 2^{u_i - C_ij} ) =====
        ((float4*)su)[tid] = __ldcg((const float4*)sk_g_u + tid);
        __syncthreads();
        {
            const float4* cb = sxc + wid * PPW;
            const float2* ub = (const float2*)su + wid * PPW;
            ull a0 = 0, a1 = 0, a2 = 0, a3 = 0;
            #pragma unroll 4
            for (int k = 0; k < PPW; k += 4) {
                sk_step(a0, cb[k + 0], ub[k + 0], Y0p, Y1p);
                sk_step(a1, cb[k + 1], ub[k + 1], Y0p, Y1p);
                sk_step(a2, cb[k + 2], ub[k + 2], Y0p, Y1p);
                sk_step(a3, cb[k + 3], ub[k + 3], Y0p, Y1p);
            }
            ull t = fadd2(fadd2(a0, a1), fadd2(a2, a3));
            float tl, th; upk(t, tl, th);
            part[wid * 33 + lane] = tl + th;
        }
        __syncthreads();
        {
            float pv = part[lane * 33 + wid];
            #pragma unroll
            for (int o = 16; o > 0; o >>= 1) pv += __shfl_xor_sync(0xffffffffu, pv, o);
            if (lane == 0) __stcg(&sk_g_v[rbase + wid], LMU2 - lg2f(pv));
        }
        grid_barrier(++phase);
    }

    // ===== final: pi = 2^{u_i + v_j - C_ij}, C, cost =====
    ((float4*)sv)[tid] = __ldcg((const float4*)sk_g_v + tid);
    ((float4*)su)[tid] = __ldcg((const float4*)sk_g_u + tid);
    __syncthreads();

    const size_t NM = (size_t)NN * NN;
    float* pi_out = out + 1;
    float* c_out  = out + 1 + NM;

    float cacc = 0.f;
    for (int r = 0; r < RPC; ++r) {
        const int i = rbase + r;
        const float Xa = x[2 * i] * SCALEF;         // L1-hot broadcast
        const float Xb = x[2 * i + 1] * SCALEF;
        const float ui = su[i];
        const size_t off = (size_t)i * NN;
        for (int q = tid; q < NN / 4; q += NT) {
            float4 ca = syc[2 * q];         // points 4q,4q+1
            float4 cb = syc[2 * q + 1];     // points 4q+2,4q+3
            float4 v4 = ((const float4*)sv)[q];
            float ct0 = fabsf(Xa + ca.x) + fabsf(Xb + ca.z);
            float ct1 = fabsf(Xa + ca.y) + fabsf(Xb + ca.w);
            float ct2 = fabsf(Xa + cb.x) + fabsf(Xb + cb.z);
            float ct3 = fabsf(Xa + cb.y) + fabsf(Xb + cb.w);
            float p0 = ex2f(ui + v4.x - ct0);
            float p1 = ex2f(ui + v4.y - ct1);
            float p2 = ex2f(ui + v4.z - ct2);
            float p3 = ex2f(ui + v4.w - ct3);
            float c0 = ct0 * INV_SCALEF, c1 = ct1 * INV_SCALEF;
            float c2 = ct2 * INV_SCALEF, c3 = ct3 * INV_SCALEF;
            const size_t b = off + 4 * (size_t)q;
            pi_out[b + 0] = p0; pi_out[b + 1] = p1; pi_out[b + 2] = p2; pi_out[b + 3] = p3;
            c_out[b + 0]  = c0; c_out[b + 1]  = c1; c_out[b + 2]  = c2; c_out[b + 3]  = c3;
            cacc += p0 * c0 + p1 * c1;
            cacc += p2 * c2 + p3 * c3;
        }
    }
    #pragma unroll
    for (int o = 16; o > 0; o >>= 1) cacc += __shfl_xor_sync(0xffffffffu, cacc, o);
    if (lane == 0) red[wid] = cacc;
    __syncthreads();
    if (wid == 0) {
        float s = red[lane];
        #pragma unroll
        for (int o = 16; o > 0; o >>= 1) s += __shfl_xor_sync(0xffffffffu, s, o);
        if (lane == 0) __stcg(&sk_g_cost[cta], s);
    }
    grid_barrier(++phase);

    if (cta == 0 && wid == 0) {
        float s = 0.f;
        #pragma unroll
        for (int b = lane; b < NCTA; b += 32) s += __ldcg(&sk_g_cost[b]);
        #pragma unroll
        for (int o = 16; o > 0; o >>= 1) s += __shfl_xor_sync(0xffffffffu, s, o);
        if (lane == 0) out[0] = s;   // cost ** (1/P), P = 1
    }
}

extern "C" void kernel_launch(void* const* d_in, const int* in_sizes, int n_in,
                              void* d_out, int out_size) {
    (void)in_sizes; (void)n_in; (void)out_size;
    const float* x = (const float*)d_in[0];
    const float* y = (const float*)d_in[1];
    float* out = (float*)d_out;

    const size_t smem = (size_t)(NN / 2) * 2 * sizeof(float4) + 2 * NN * sizeof(float); // 96KB
    cudaFuncSetAttribute(sk_persist_kernel,
                         cudaFuncAttributeMaxDynamicSharedMemorySize, (int)smem);

    sk_init_kernel<<<8, 512>>>();
    sk_persist_kernel<<<NCTA, NT, smem>>>(x, y, out);
}